// round 1
// baseline (speedup 1.0000x reference)
#include <cuda_runtime.h>

// Problem constants
#define BATCH   32768
#define HID     128
#define INF     784
#define NCLS    10
#define TSTEPS  20

#define DECAYF     0.25f
#define THRESHF    1.0f

// Scratch (device globals: allocation-free rule)
__device__ float g_cur1[(size_t)BATCH * HID];            // 16.8 MB
__device__ float g_c2[(size_t)TSTEPS * BATCH * NCLS];    // 26.2 MB

// ---------------------------------------------------------------------------
// K1: cur1 = x @ W1^T + b1    (M=32768, N=128, K=784), fp32, sequential-k FMA
// Block computes a 128x128 tile; 256 threads, 8x8 per thread.
// ---------------------------------------------------------------------------
__global__ __launch_bounds__(256) void k1_gemm1(
    const float* __restrict__ x, const float* __restrict__ W1,
    const float* __restrict__ b1)
{
    __shared__ float As[16][128];   // [k][m]
    __shared__ float Bs[16][128];   // [k][n]

    const int tid = threadIdx.x;
    const int tx  = tid & 15;       // n group
    const int ty  = tid >> 4;       // m group
    const int m0  = blockIdx.x * 128;

    float acc[8][8];
    #pragma unroll
    for (int i = 0; i < 8; i++)
        #pragma unroll
        for (int j = 0; j < 8; j++) acc[i][j] = 0.0f;

    for (int k0 = 0; k0 < INF; k0 += 16) {
        // Load A tile: x[m0+m][k0+k], 2048 floats as 512 float4
        #pragma unroll
        for (int it = 0; it < 2; it++) {
            int f  = tid + it * 256;        // 0..511
            int m  = f >> 2;
            int kq = (f & 3) * 4;
            float4 v = *reinterpret_cast<const float4*>(&x[(size_t)(m0 + m) * INF + k0 + kq]);
            As[kq + 0][m] = v.x; As[kq + 1][m] = v.y;
            As[kq + 2][m] = v.z; As[kq + 3][m] = v.w;
        }
        // Load B tile: W1[n][k0+k]
        #pragma unroll
        for (int it = 0; it < 2; it++) {
            int f  = tid + it * 256;
            int n  = f >> 2;
            int kq = (f & 3) * 4;
            float4 v = *reinterpret_cast<const float4*>(&W1[(size_t)n * INF + k0 + kq]);
            Bs[kq + 0][n] = v.x; Bs[kq + 1][n] = v.y;
            Bs[kq + 2][n] = v.z; Bs[kq + 3][n] = v.w;
        }
        __syncthreads();

        #pragma unroll
        for (int k = 0; k < 16; k++) {
            float4 a0 = *reinterpret_cast<const float4*>(&As[k][ty * 8]);
            float4 a1 = *reinterpret_cast<const float4*>(&As[k][ty * 8 + 4]);
            float4 b0 = *reinterpret_cast<const float4*>(&Bs[k][tx * 8]);
            float4 b1v = *reinterpret_cast<const float4*>(&Bs[k][tx * 8 + 4]);
            float a[8] = {a0.x, a0.y, a0.z, a0.w, a1.x, a1.y, a1.z, a1.w};
            float b[8] = {b0.x, b0.y, b0.z, b0.w, b1v.x, b1v.y, b1v.z, b1v.w};
            #pragma unroll
            for (int i = 0; i < 8; i++)
                #pragma unroll
                for (int j = 0; j < 8; j++)
                    acc[i][j] = fmaf(a[i], b[j], acc[i][j]);
        }
        __syncthreads();
    }

    // Epilogue: + b1 (single rounding, after full dot), store
    float bb[8];
    #pragma unroll
    for (int j = 0; j < 8; j++) bb[j] = __ldg(&b1[tx * 8 + j]);

    #pragma unroll
    for (int i = 0; i < 8; i++) {
        int m = m0 + ty * 8 + i;
        float4 v0, v1;
        v0.x = acc[i][0] + bb[0]; v0.y = acc[i][1] + bb[1];
        v0.z = acc[i][2] + bb[2]; v0.w = acc[i][3] + bb[3];
        v1.x = acc[i][4] + bb[4]; v1.y = acc[i][5] + bb[5];
        v1.z = acc[i][6] + bb[6]; v1.w = acc[i][7] + bb[7];
        *reinterpret_cast<float4*>(&g_cur1[(size_t)m * HID + tx * 8])     = v0;
        *reinterpret_cast<float4*>(&g_cur1[(size_t)m * HID + tx * 8 + 4]) = v1;
    }
}

// ---------------------------------------------------------------------------
// K2: layer-1 LIF dynamics, elementwise over (b,j), writes spk1_rec [T,B,H]
// Each thread: 4 consecutive channels (float4).
// ---------------------------------------------------------------------------
__global__ __launch_bounds__(256) void k2_lif1(float* __restrict__ out_spk)
{
    const int i = blockIdx.x * blockDim.x + threadIdx.x;   // over BATCH*HID/4
    const float4 c = reinterpret_cast<const float4*>(g_cur1)[i];

    float mx = 0.0f, my = 0.0f, mz = 0.0f, mw = 0.0f;
    #pragma unroll
    for (int t = 0; t < TSTEPS; t++) {
        // mem = mem*0.25 + cur  (x0.25 exact -> FMA == reference rounding)
        mx = fmaf(mx, DECAYF, c.x);
        my = fmaf(my, DECAYF, c.y);
        mz = fmaf(mz, DECAYF, c.z);
        mw = fmaf(mw, DECAYF, c.w);
        float4 s;
        s.x = (mx > THRESHF) ? 1.0f : 0.0f;
        s.y = (my > THRESHF) ? 1.0f : 0.0f;
        s.z = (mz > THRESHF) ? 1.0f : 0.0f;
        s.w = (mw > THRESHF) ? 1.0f : 0.0f;
        float* p = out_spk + (size_t)t * (BATCH * HID);
        reinterpret_cast<float4*>(p)[i] = s;
        // mem *= (1 - spk): exact select
        mx = (s.x != 0.0f) ? 0.0f : mx;
        my = (s.y != 0.0f) ? 0.0f : my;
        mz = (s.z != 0.0f) ? 0.0f : mz;
        mw = (s.w != 0.0f) ? 0.0f : mw;
    }
}

// ---------------------------------------------------------------------------
// K3: c2[row, o] = spk[row,:] @ W2[o,:]   (row = t*BATCH + b, K=128, N=10)
// 256 rows per block, smem-staged 32-wide j chunks (coalesced gmem loads).
// ---------------------------------------------------------------------------
__global__ __launch_bounds__(256) void k3_gemm2(
    const float* __restrict__ spk, const float* __restrict__ W2)
{
    __shared__ float sh[256][33];     // pad 33: conflict-free row reads
    __shared__ float W2s[NCLS * HID];

    const int tid = threadIdx.x;
    for (int i = tid; i < NCLS * HID; i += 256) W2s[i] = W2[i];

    const size_t row0 = (size_t)blockIdx.x * 256;
    float acc[NCLS];
    #pragma unroll
    for (int o = 0; o < NCLS; o++) acc[o] = 0.0f;

    for (int jc = 0; jc < 4; jc++) {
        __syncthreads();
        #pragma unroll
        for (int s4 = 0; s4 < 8; s4++) {
            int f = tid + s4 * 256;   // 0..2047 float4 slots
            int r = f >> 3;
            int q = f & 7;
            float4 v = *reinterpret_cast<const float4*>(
                &spk[(row0 + r) * HID + jc * 32 + q * 4]);
            sh[r][q * 4 + 0] = v.x; sh[r][q * 4 + 1] = v.y;
            sh[r][q * 4 + 2] = v.z; sh[r][q * 4 + 3] = v.w;
        }
        __syncthreads();
        #pragma unroll
        for (int j = 0; j < 32; j++) {
            float s = sh[tid][j];
            #pragma unroll
            for (int o = 0; o < NCLS; o++)
                acc[o] = fmaf(s, W2s[o * HID + jc * 32 + j], acc[o]);
        }
    }

    const size_t r = row0 + tid;
    #pragma unroll
    for (int o = 0; o < NCLS; o++)
        g_c2[r * NCLS + o] = acc[o];
}

// ---------------------------------------------------------------------------
// K4: layer-2 recurrence + output.  mem2 = (mem2*0.25 + c2) + b2 (ref order).
// ---------------------------------------------------------------------------
__global__ __launch_bounds__(256) void k4_lif2(
    const float* __restrict__ b2, float* __restrict__ outp)
{
    const int id = blockIdx.x * blockDim.x + threadIdx.x;  // over BATCH*NCLS
    const int o = id % NCLS;
    const float bias = __ldg(&b2[o]);

    float mem = 0.0f, acc = 0.0f;
    #pragma unroll
    for (int t = 0; t < TSTEPS; t++) {
        float v = fmaf(mem, DECAYF, g_c2[(size_t)t * (BATCH * NCLS) + id]);
        v = v + bias;                       // separate add, matches ref order
        float s = (v > THRESHF) ? 1.0f : 0.0f;
        acc += s;
        mem = (s != 0.0f) ? 0.0f : v;
    }
    outp[id] = acc;
}

// ---------------------------------------------------------------------------
extern "C" void kernel_launch(void* const* d_in, const int* in_sizes, int n_in,
                              void* d_out, int out_size)
{
    const float* x  = (const float*)d_in[0];
    const float* W1 = (const float*)d_in[1];
    const float* b1 = (const float*)d_in[2];
    const float* W2 = (const float*)d_in[3];
    const float* b2 = (const float*)d_in[4];
    float* out = (float*)d_out;

    float* out_output = out;                          // [BATCH, NCLS]
    float* out_spk    = out + (size_t)BATCH * NCLS;   // [T, BATCH, HID]

    k1_gemm1<<<BATCH / 128, 256>>>(x, W1, b1);
    k2_lif1<<<(BATCH * HID / 4) / 256, 256>>>(out_spk);
    k3_gemm2<<<(TSTEPS * BATCH) / 256, 256>>>(out_spk, W2);
    k4_lif2<<<(BATCH * NCLS) / 256, 256>>>(b2, out_output);
}